// round 1
// baseline (speedup 1.0000x reference)
#include <cuda_runtime.h>

#define CHANNELS 256
#define HW 4096          // 64*64
#define BATCH 2
#define PYR_COLS 5440    // 4096 + 1024 + 256 + 64
// level column offsets within one batch of the pyramid
// L0: 0 (64x64) L1: 4096 (32x32) L2: 5120 (16x16) L3: 5376 (8x8)

__device__ __align__(16) float g_f1t[BATCH * HW * CHANNELS];        // 8 MB  [b][pix][c], pre-scaled by 1/16
__device__ __align__(16) float g_f2p[BATCH * PYR_COLS * CHANNELS];  // ~11 MB [b][col][c]

// ---------------------------------------------------------------------------
// Transpose [B][C][P] -> [B][P][C] (which==0 -> g_f1t with 1/16 scale,
// which==1 -> g_f2p level-0 region, scale 1)
// grid (P/32, C/32, B), block (32, 8)
// ---------------------------------------------------------------------------
__global__ void transpose_cp(const float* __restrict__ src, int which) {
    __shared__ float tile[32][33];
    float* dst = which ? g_f2p : g_f1t;
    const float scale = which ? 1.0f : 0.0625f;   // 1/sqrt(256) folded into f1
    const int dst_bstride = which ? (PYR_COLS * CHANNELS) : (HW * CHANNELS);

    const int b  = blockIdx.z;
    const int p0 = blockIdx.x * 32;
    const int c0 = blockIdx.y * 32;
    const float* s = src + b * CHANNELS * HW;

    #pragma unroll
    for (int r = threadIdx.y; r < 32; r += 8)
        tile[r][threadIdx.x] = s[(c0 + r) * HW + p0 + threadIdx.x] * scale;
    __syncthreads();

    float* d = dst + b * dst_bstride;
    #pragma unroll
    for (int r = threadIdx.y; r < 32; r += 8)
        d[(p0 + r) * CHANNELS + c0 + threadIdx.x] = tile[threadIdx.x][r];
}

// ---------------------------------------------------------------------------
// 2x2 average pool on pyramid columns: level (2S x 2S) -> (S x S)
// grid = B*S*S blocks, 256 threads (thread = channel)
// ---------------------------------------------------------------------------
__global__ void pool_level(int src_off, int dst_off, int S) {
    const int col = blockIdx.x;
    const int b   = col / (S * S);
    const int r   = col - b * S * S;
    const int Y   = r / S, X = r - Y * S;
    const int c   = threadIdx.x;

    const float* s = g_f2p + (b * PYR_COLS + src_off + (2 * Y) * (2 * S) + 2 * X) * CHANNELS;
    float v = s[c] + s[CHANNELS + c]
            + s[(2 * S) * CHANNELS + c] + s[(2 * S) * CHANNELS + CHANNELS + c];
    g_f2p[(b * PYR_COLS + dst_off + r) * CHANNELS + c] = 0.25f * v;
}

// ---------------------------------------------------------------------------
// Main kernel: one warp per query pixel, 8 pixels per CTA.
// Per (pixel, level): compute 10x10 corner grid of dot-products against the
// pooled f2 pyramid (8 lanes per column, 4 columns in flight per warp), then
// bilinearly interpolate 81 samples from the grid.
// ---------------------------------------------------------------------------
__global__ void __launch_bounds__(256) corr_sample(const float* __restrict__ cc,
                                                   float* __restrict__ out) {
    const int tid  = threadIdx.x;
    const int warp = tid >> 5;
    const int lane = tid & 31;
    const int p    = blockIdx.x * 8 + warp;   // global pixel id 0..8191
    const int b    = p >> 12;
    const int pix  = p & 4095;

    __shared__ float G[8][4][100];    // corner grids: [pixel][level][10*10]
    __shared__ float OB[8][324];      // staged outputs: [pixel][channel]

    const int sub = lane & 7;         // channel-chunk within column group
    const int q   = lane >> 3;        // which of 4 concurrent columns

    // f1 slice for this pixel: 32 channels per lane (lanes q*8+sub share data)
    float a[32];
    {
        const float4* f1 = (const float4*)(g_f1t + p * CHANNELS + sub * 32);
        #pragma unroll
        for (int k = 0; k < 8; k++) {
            float4 v = f1[k];
            a[4 * k] = v.x; a[4 * k + 1] = v.y; a[4 * k + 2] = v.z; a[4 * k + 3] = v.w;
        }
    }

    const float cx = cc[(b * 2 + 0) * HW + pix];
    const float cy = cc[(b * 2 + 1) * HW + pix];

    const float* f2b = g_f2p + b * PYR_COLS * CHANNELS;
    const int off[4] = {0, 4096, 5120, 5376};

    #pragma unroll
    for (int lvl = 0; lvl < 4; lvl++) {
        const int   size = 64 >> lvl;
        const float inv  = 1.0f / (float)(1 << lvl);
        const float cxl  = cx * inv, cyl = cy * inv;
        const int   ix0  = (int)floorf(cxl) - 4;
        const int   iy0  = (int)floorf(cyl) - 4;
        const float* base = f2b + off[lvl] * CHANNELS;

        #pragma unroll 5
        for (int cblk = 0; cblk < 100; cblk += 4) {
            const int c = cblk + q;                 // 0..99
            const int j = c / 10, i = c - j * 10;
            const int ix = ix0 + i, iy = iy0 + j;
            const bool valid = ((unsigned)ix < (unsigned)size) &&
                               ((unsigned)iy < (unsigned)size);
            const int col = valid ? (iy * size + ix) : 0;

            const float4* fp = (const float4*)(base + col * CHANNELS + sub * 32);
            float s = 0.0f;
            #pragma unroll
            for (int k = 0; k < 8; k++) {
                float4 v = fp[k];
                s += a[4 * k] * v.x + a[4 * k + 1] * v.y
                   + a[4 * k + 2] * v.z + a[4 * k + 3] * v.w;
            }
            // reduce over the 8 lanes of this column group
            s += __shfl_xor_sync(0xffffffffu, s, 1);
            s += __shfl_xor_sync(0xffffffffu, s, 2);
            s += __shfl_xor_sync(0xffffffffu, s, 4);
            if (sub == 0) G[warp][lvl][c] = valid ? s : 0.0f;
        }
    }
    __syncwarp();

    // interpolate 81 samples per level from the corner grids
    #pragma unroll
    for (int lvl = 0; lvl < 4; lvl++) {
        const float inv = 1.0f / (float)(1 << lvl);
        const float cxl = cx * inv, cyl = cy * inv;
        const float fx  = cxl - floorf(cxl);
        const float fy  = cyl - floorf(cyl);
        for (int s = lane; s < 81; s += 32) {
            const int si = s / 9, sj = s - si * 9;  // si -> x offset, sj -> y offset
            const float g00 = G[warp][lvl][sj * 10 + si];
            const float g01 = G[warp][lvl][sj * 10 + si + 1];
            const float g10 = G[warp][lvl][(sj + 1) * 10 + si];
            const float g11 = G[warp][lvl][(sj + 1) * 10 + si + 1];
            const float v = (1.0f - fy) * ((1.0f - fx) * g00 + fx * g01)
                          +          fy * ((1.0f - fx) * g10 + fx * g11);
            OB[warp][lvl * 81 + s] = v;
        }
    }
    __syncthreads();

    // coalesced store: 8 consecutive pixels of one channel = 32B
    const int pix0 = (blockIdx.x * 8) & 4095;
    const int bb   = (blockIdx.x * 8) >> 12;
    for (int idx = tid; idx < 324 * 8; idx += 256) {
        const int ch = idx >> 3;
        const int pp = idx & 7;
        out[(bb * 324 + ch) * HW + pix0 + pp] = OB[pp][ch];
    }
}

// ---------------------------------------------------------------------------
extern "C" void kernel_launch(void* const* d_in, const int* in_sizes, int n_in,
                              void* d_out, int out_size) {
    const float* fmap1 = (const float*)d_in[0];
    const float* fmap2 = (const float*)d_in[1];
    const float* cc    = (const float*)d_in[2];
    float* out = (float*)d_out;

    dim3 tgrid(HW / 32, CHANNELS / 32, BATCH);
    dim3 tblk(32, 8);
    transpose_cp<<<tgrid, tblk>>>(fmap1, 0);   // f1 transposed + scaled 1/16
    transpose_cp<<<tgrid, tblk>>>(fmap2, 1);   // f2 level 0

    pool_level<<<BATCH * 32 * 32, CHANNELS>>>(0,    4096, 32);
    pool_level<<<BATCH * 16 * 16, CHANNELS>>>(4096, 5120, 16);
    pool_level<<<BATCH * 8 * 8,   CHANNELS>>>(5120, 5376, 8);

    corr_sample<<<(BATCH * HW) / 8, 256>>>(cc, out);
}

// round 3
// speedup vs baseline: 6.0443x; 6.0443x over previous
#include <cuda_runtime.h>
#include <cuda_fp16.h>
#include <cstdint>

#define CHANNELS 256
#define HW 4096
#define BATCH 2
#define NPAD 5504              // 43 * 128 padded pyramid cols
#define NREAL 5440             // 4096 + 1024 + 256 + 64
// level offsets: L0 0 (64x64), L1 4096 (32x32), L2 5120 (16x16), L3 5376 (8x8)

__device__ __align__(16) __half g_f1h[BATCH * HW * CHANNELS];     // [b][m][k], scaled 1/16
__device__ __align__(16) __half g_f2h[BATCH * NPAD * CHANNELS];   // [b][n][k]
__device__ __align__(16) float  g_C[(size_t)BATCH * HW * NPAD];   // corr volume (~180 MB)

// ===================== helpers ========================
__device__ __forceinline__ uint32_t smem_u32(const void* p) {
    uint32_t a;
    asm("{ .reg .u64 t; cvta.to.shared.u64 t, %1; cvt.u32.u64 %0, t; }" : "=r"(a) : "l"(p));
    return a;
}
__device__ __forceinline__ void cp_async16(uint32_t s, const void* g) {
    asm volatile("cp.async.cg.shared.global [%0], [%1], 16;" :: "r"(s), "l"(g));
}
__device__ __forceinline__ void cp_commit() { asm volatile("cp.async.commit_group;"); }
template <int N> __device__ __forceinline__ void cp_wait() {
    asm volatile("cp.async.wait_group %0;" :: "n"(N));
}
__device__ __forceinline__ void ldsm_x4(uint32_t* r, uint32_t addr) {
    asm volatile("ldmatrix.sync.aligned.m8n8.x4.shared.b16 {%0,%1,%2,%3}, [%4];"
                 : "=r"(r[0]), "=r"(r[1]), "=r"(r[2]), "=r"(r[3]) : "r"(addr));
}
__device__ __forceinline__ void ldsm_x2(uint32_t* r, uint32_t addr) {
    asm volatile("ldmatrix.sync.aligned.m8n8.x2.shared.b16 {%0,%1}, [%2];"
                 : "=r"(r[0]), "=r"(r[1]) : "r"(addr));
}
__device__ __forceinline__ void mma16816(float* c, const uint32_t* a, const uint32_t* b) {
    asm volatile("mma.sync.aligned.m16n8k16.row.col.f32.f16.f16.f32 "
                 "{%0,%1,%2,%3}, {%4,%5,%6,%7}, {%8,%9}, {%0,%1,%2,%3};"
                 : "+f"(c[0]), "+f"(c[1]), "+f"(c[2]), "+f"(c[3])
                 : "r"(a[0]), "r"(a[1]), "r"(a[2]), "r"(a[3]), "r"(b[0]), "r"(b[1]));
}

// ======================= prep: transpose + fp16 convert =====================
// [B][C][P] fp32 -> [B][P][C] fp16. which==0 -> g_f1h (scale 1/16), 1 -> g_f2h L0
__global__ void cvt_transpose(const float* __restrict__ src, int which) {
    __shared__ float tile[32][33];
    __half* dst = which ? g_f2h : g_f1h;
    const float scale = which ? 1.0f : 0.0625f;      // 1/sqrt(256) folded into f1
    const int bstride = which ? (NPAD * CHANNELS) : (HW * CHANNELS);

    const int b = blockIdx.z, p0 = blockIdx.x * 32, c0 = blockIdx.y * 32;
    const float* s = src + (size_t)b * CHANNELS * HW;
    #pragma unroll
    for (int r = threadIdx.y; r < 32; r += 8)
        tile[r][threadIdx.x] = s[(c0 + r) * HW + p0 + threadIdx.x] * scale;
    __syncthreads();
    __half* d = dst + (size_t)b * bstride;
    #pragma unroll
    for (int r = threadIdx.y; r < 32; r += 8)
        d[(p0 + r) * CHANNELS + c0 + threadIdx.x] = __float2half(tile[threadIdx.x][r]);
}

// 2x2 avg pool on fp16 pyramid columns
__global__ void pool_level(int src_off, int dst_off, int S) {
    const int col = blockIdx.x;
    const int b = col / (S * S);
    const int r = col - b * S * S;
    const int Y = r / S, X = r - Y * S;
    const int c = threadIdx.x;
    const __half* s = g_f2h + ((size_t)b * NPAD + src_off + (2 * Y) * (2 * S) + 2 * X) * CHANNELS;
    float v = __half2float(s[c]) + __half2float(s[CHANNELS + c]) +
              __half2float(s[(2 * S) * CHANNELS + c]) +
              __half2float(s[(2 * S) * CHANNELS + CHANNELS + c]);
    g_f2h[((size_t)b * NPAD + dst_off + r) * CHANNELS + c] = __float2half(0.25f * v);
}

__global__ void zero_pad() {
    int i = blockIdx.x * 256 + threadIdx.x;          // 2 * 64 * 256 = 32768
    int b = i >> 14;
    int r = i & 16383;
    g_f2h[((size_t)b * NPAD + NREAL) * CHANNELS + r] = __float2half(0.0f);
}

// ============================ HMMA GEMM =====================================
// C[b][m][n] = sum_k f1h[b][m][k] * f2h[b][n][k]
// CTA tile 128x128, BK=32, 8 warps (2x4), warp tile 64x32, cp.async 2-stage.
#define BK 32
#define SRB 80                 // smem row stride in bytes (32 halves + 8 pad)
#define TILE_B (128 * SRB)     // 10240 bytes per operand per stage

__global__ void __launch_bounds__(256) gemm_tile() {
    __shared__ __align__(16) char smem[4 * TILE_B];   // A0 B0 A1 B1

    const int tid = threadIdx.x, wid = tid >> 5, lane = tid & 31;
    const int nt = blockIdx.x, mt = blockIdx.y, b = blockIdx.z;
    const int wm = wid & 1, wn = wid >> 1;            // warp coords (2 x 4)

    const uint32_t sbase = smem_u32(smem);
    const __half* Ag = g_f1h + ((size_t)b * HW + mt * 128) * CHANNELS;
    const __half* Bg = g_f2h + ((size_t)b * NPAD + nt * 128) * CHANNELS;

    // per-thread cp.async assignment: 2 chunks of 16B for A, 2 for B per stage
    // chunk q in [0,512): row = q>>2, c = q&3  (c = 16B chunk within 64B row)
    const int q0 = tid * 2, q1 = tid * 2 + 1;
    const int r0 = q0 >> 2, c0 = q0 & 3;
    const int r1 = q1 >> 2, c1 = q1 & 3;

    float acc[4][4][4];
    #pragma unroll
    for (int i = 0; i < 4; i++)
        #pragma unroll
        for (int j = 0; j < 4; j++)
            #pragma unroll
            for (int k = 0; k < 4; k++) acc[i][j][k] = 0.0f;

    auto issue = [&](int kt, int stage) {
        const uint32_t sA = sbase + stage * 2 * TILE_B;
        const uint32_t sB = sA + TILE_B;
        const int kh = kt * BK;                       // k offset in halves
        cp_async16(sA + r0 * SRB + c0 * 16, Ag + r0 * CHANNELS + kh + c0 * 8);
        cp_async16(sA + r1 * SRB + c1 * 16, Ag + r1 * CHANNELS + kh + c1 * 8);
        cp_async16(sB + r0 * SRB + c0 * 16, Bg + r0 * CHANNELS + kh + c0 * 8);
        cp_async16(sB + r1 * SRB + c1 * 16, Bg + r1 * CHANNELS + kh + c1 * 8);
        cp_commit();
    };

    issue(0, 0);

    // ldmatrix base offsets
    const int a_row = wm * 64 + (lane & 15);          // + mi*16
    const int a_kh  = (lane >> 4) * 8;                // + s*16 (halves)
    const int b_row = wn * 32 + (lane & 7);           // + ni*8
    const int b_kh  = ((lane >> 3) & 1) * 8;          // + s*16

    #pragma unroll
    for (int kt = 0; kt < 8; kt++) {
        const int stage = kt & 1;
        if (kt < 7) issue(kt + 1, stage ^ 1);
        if (kt < 7) cp_wait<1>(); else cp_wait<0>();
        __syncthreads();

        const uint32_t sA = sbase + stage * 2 * TILE_B;
        const uint32_t sB = sA + TILE_B;

        #pragma unroll
        for (int s = 0; s < 2; s++) {                 // two k16 steps per BK
            uint32_t afr[4][4], bfr[4][2];
            #pragma unroll
            for (int mi = 0; mi < 4; mi++)
                ldsm_x4(afr[mi], sA + (a_row + mi * 16) * SRB + (a_kh + s * 16) * 2);
            #pragma unroll
            for (int ni = 0; ni < 4; ni++)
                ldsm_x2(bfr[ni], sB + (b_row + ni * 8) * SRB + (b_kh + s * 16) * 2);
            #pragma unroll
            for (int mi = 0; mi < 4; mi++)
                #pragma unroll
                for (int ni = 0; ni < 4; ni++)
                    mma16816(acc[mi][ni], afr[mi], bfr[ni]);
        }
        __syncthreads();
    }

    // epilogue: direct float2 stores (each 4-lane group covers a 32B sector)
    const int gid = lane >> 2, tig = lane & 3;
    #pragma unroll
    for (int mi = 0; mi < 4; mi++) {
        const size_t row = (size_t)b * HW + mt * 128 + wm * 64 + mi * 16 + gid;
        float* Cr = g_C + row * NPAD + nt * 128 + wn * 32 + tig * 2;
        #pragma unroll
        for (int ni = 0; ni < 4; ni++) {
            float2 v0 = make_float2(acc[mi][ni][0], acc[mi][ni][1]);
            float2 v1 = make_float2(acc[mi][ni][2], acc[mi][ni][3]);
            *(float2*)(Cr + ni * 8) = v0;
            *(float2*)(Cr + 8 * NPAD + ni * 8) = v1;
        }
    }
}

// ============================ sampler =======================================
// One warp per pixel, 8 pixels/CTA: gather 10x10 corner grids from g_C rows,
// bilinear-interp 81 samples/level, coalesced channel-major store.
__global__ void __launch_bounds__(256) corr_sample(const float* __restrict__ cc,
                                                   float* __restrict__ out) {
    const int tid = threadIdx.x, warp = tid >> 5, lane = tid & 31;
    const int p = blockIdx.x * 8 + warp;
    const int b = p >> 12, pix = p & 4095;

    __shared__ float G[8][4][100];
    __shared__ float OB[8][324];

    const float cx = cc[(b * 2 + 0) * HW + pix];
    const float cy = cc[(b * 2 + 1) * HW + pix];
    const float* Crow = g_C + ((size_t)b * HW + pix) * NPAD;
    const int off[4] = {0, 4096, 5120, 5376};

    #pragma unroll
    for (int lvl = 0; lvl < 4; lvl++) {
        const int size = 64 >> lvl;
        const float inv = 1.0f / (float)(1 << lvl);
        const float cxl = cx * inv, cyl = cy * inv;
        const int ix0 = (int)floorf(cxl) - 4;
        const int iy0 = (int)floorf(cyl) - 4;
        const float* base = Crow + off[lvl];
        #pragma unroll
        for (int c = lane; c < 100; c += 32) {
            const int j = c / 10, i = c - j * 10;
            const int ix = ix0 + i, iy = iy0 + j;
            const bool valid = ((unsigned)ix < (unsigned)size) && ((unsigned)iy < (unsigned)size);
            G[warp][lvl][c] = valid ? base[iy * size + ix] : 0.0f;
        }
    }
    __syncwarp();

    #pragma unroll
    for (int lvl = 0; lvl < 4; lvl++) {
        const float inv = 1.0f / (float)(1 << lvl);
        const float cxl = cx * inv, cyl = cy * inv;
        const float fx = cxl - floorf(cxl);
        const float fy = cyl - floorf(cyl);
        for (int s = lane; s < 81; s += 32) {
            const int si = s / 9, sj = s - si * 9;   // si -> x offset, sj -> y offset
            const float g00 = G[warp][lvl][sj * 10 + si];
            const float g01 = G[warp][lvl][sj * 10 + si + 1];
            const float g10 = G[warp][lvl][(sj + 1) * 10 + si];
            const float g11 = G[warp][lvl][(sj + 1) * 10 + si + 1];
            OB[warp][lvl * 81 + s] = (1.0f - fy) * ((1.0f - fx) * g00 + fx * g01)
                                   + fy * ((1.0f - fx) * g10 + fx * g11);
        }
    }
    __syncthreads();

    const int pix0 = (blockIdx.x * 8) & 4095;
    const int bb = (blockIdx.x * 8) >> 12;
    for (int idx = tid; idx < 324 * 8; idx += 256) {
        const int ch = idx >> 3, pp = idx & 7;
        out[((size_t)bb * 324 + ch) * HW + pix0 + pp] = OB[pp][ch];
    }
}

// ===========================================================================
extern "C" void kernel_launch(void* const* d_in, const int* in_sizes, int n_in,
                              void* d_out, int out_size) {
    const float* fmap1 = (const float*)d_in[0];
    const float* fmap2 = (const float*)d_in[1];
    const float* cc    = (const float*)d_in[2];
    float* out = (float*)d_out;

    dim3 tgrid(HW / 32, CHANNELS / 32, BATCH);
    dim3 tblk(32, 8);
    cvt_transpose<<<tgrid, tblk>>>(fmap1, 0);
    cvt_transpose<<<tgrid, tblk>>>(fmap2, 1);

    pool_level<<<BATCH * 32 * 32, CHANNELS>>>(0,    4096, 32);
    pool_level<<<BATCH * 16 * 16, CHANNELS>>>(4096, 5120, 16);
    pool_level<<<BATCH * 8 * 8,   CHANNELS>>>(5120, 5376, 8);
    zero_pad<<<128, 256>>>();

    gemm_tile<<<dim3(43, 32, BATCH), 256>>>();

    corr_sample<<<(BATCH * HW) / 8, 256>>>(cc, out);
}

// round 4
// speedup vs baseline: 6.3415x; 1.0492x over previous
#include <cuda_runtime.h>
#include <cuda_fp16.h>
#include <cstdint>

#define CHANNELS 256
#define HW 4096
#define BATCH 2
#define NPAD 5504              // 43 * 128 padded pyramid cols
#define NREAL 5440             // 4096 + 1024 + 256 + 64
// level offsets: L0 0 (64x64), L1 4096 (32x32), L2 5120 (16x16), L3 5376 (8x8)

__device__ __align__(16) __half g_f1h[BATCH * HW * CHANNELS];     // [b][m][k], scaled 1/16
__device__ __align__(16) __half g_f2h[BATCH * NPAD * CHANNELS];   // [b][n][k]
__device__ __align__(16) __half g_C[(size_t)BATCH * HW * NPAD];   // corr volume (~90 MB, fp16)

// ===================== helpers ========================
__device__ __forceinline__ uint32_t smem_u32(const void* p) {
    uint32_t a;
    asm("{ .reg .u64 t; cvta.to.shared.u64 t, %1; cvt.u32.u64 %0, t; }" : "=r"(a) : "l"(p));
    return a;
}
__device__ __forceinline__ void cp_async16(uint32_t s, const void* g) {
    asm volatile("cp.async.cg.shared.global [%0], [%1], 16;" :: "r"(s), "l"(g));
}
__device__ __forceinline__ void cp_commit() { asm volatile("cp.async.commit_group;"); }
template <int N> __device__ __forceinline__ void cp_wait() {
    asm volatile("cp.async.wait_group %0;" :: "n"(N));
}
__device__ __forceinline__ void ldsm_x4(uint32_t* r, uint32_t addr) {
    asm volatile("ldmatrix.sync.aligned.m8n8.x4.shared.b16 {%0,%1,%2,%3}, [%4];"
                 : "=r"(r[0]), "=r"(r[1]), "=r"(r[2]), "=r"(r[3]) : "r"(addr));
}
__device__ __forceinline__ void ldsm_x2(uint32_t* r, uint32_t addr) {
    asm volatile("ldmatrix.sync.aligned.m8n8.x2.shared.b16 {%0,%1}, [%2];"
                 : "=r"(r[0]), "=r"(r[1]) : "r"(addr));
}
__device__ __forceinline__ void mma16816(float* c, const uint32_t* a, const uint32_t* b) {
    asm volatile("mma.sync.aligned.m16n8k16.row.col.f32.f16.f16.f32 "
                 "{%0,%1,%2,%3}, {%4,%5,%6,%7}, {%8,%9}, {%0,%1,%2,%3};"
                 : "+f"(c[0]), "+f"(c[1]), "+f"(c[2]), "+f"(c[3])
                 : "r"(a[0]), "r"(a[1]), "r"(a[2]), "r"(a[3]), "r"(b[0]), "r"(b[1]));
}

// ======================= prep: transpose + fp16 convert =====================
// [B][C][P] fp32 -> [B][P][C] fp16. which==0 -> g_f1h (scale 1/16), 1 -> g_f2h L0
__global__ void cvt_transpose(const float* __restrict__ src, int which) {
    __shared__ float tile[32][33];
    __half* dst = which ? g_f2h : g_f1h;
    const float scale = which ? 1.0f : 0.0625f;      // 1/sqrt(256) folded into f1
    const int bstride = which ? (NPAD * CHANNELS) : (HW * CHANNELS);

    const int b = blockIdx.z, p0 = blockIdx.x * 32, c0 = blockIdx.y * 32;
    const float* s = src + (size_t)b * CHANNELS * HW;
    #pragma unroll
    for (int r = threadIdx.y; r < 32; r += 8)
        tile[r][threadIdx.x] = s[(c0 + r) * HW + p0 + threadIdx.x] * scale;
    __syncthreads();
    __half* d = dst + (size_t)b * bstride;
    #pragma unroll
    for (int r = threadIdx.y; r < 32; r += 8)
        d[(p0 + r) * CHANNELS + c0 + threadIdx.x] = __float2half(tile[threadIdx.x][r]);
}

// 2x2 avg pool on fp16 pyramid columns
__global__ void pool_level(int src_off, int dst_off, int S) {
    const int col = blockIdx.x;
    const int b = col / (S * S);
    const int r = col - b * S * S;
    const int Y = r / S, X = r - Y * S;
    const int c = threadIdx.x;
    const __half* s = g_f2h + ((size_t)b * NPAD + src_off + (2 * Y) * (2 * S) + 2 * X) * CHANNELS;
    float v = __half2float(s[c]) + __half2float(s[CHANNELS + c]) +
              __half2float(s[(2 * S) * CHANNELS + c]) +
              __half2float(s[(2 * S) * CHANNELS + CHANNELS + c]);
    g_f2h[((size_t)b * NPAD + dst_off + r) * CHANNELS + c] = __float2half(0.25f * v);
}

__global__ void zero_pad() {
    int i = blockIdx.x * 256 + threadIdx.x;          // 2 * 64 * 256 = 32768
    int b = i >> 14;
    int r = i & 16383;
    g_f2h[((size_t)b * NPAD + NREAL) * CHANNELS + r] = __float2half(0.0f);
}

// ============================ HMMA GEMM =====================================
// C[b][m][n] = sum_k f1h[b][m][k] * f2h[b][n][k]   (fp16 output)
// CTA tile 128x128, BK=32, 8 warps (2x4), warp tile 64x32,
// 3-stage cp.async pipeline, one __syncthreads per k-iteration.
#define BK 32
#define SRB 80                 // smem row stride in bytes (32 halves + 8 pad)
#define TILE_B (128 * SRB)     // 10240 bytes per operand per stage
#define GEMM_SMEM (6 * TILE_B) // 3 stages x (A + B) = 61440 B

__global__ void __launch_bounds__(256) gemm_tile() {
    extern __shared__ __align__(16) char smem[];

    const int tid = threadIdx.x, wid = tid >> 5, lane = tid & 31;
    const int nt = blockIdx.x, mt = blockIdx.y, b = blockIdx.z;
    const int wm = wid & 1, wn = wid >> 1;            // warp coords (2 x 4)

    const uint32_t sbase = smem_u32(smem);
    const __half* Ag = g_f1h + ((size_t)b * HW + mt * 128) * CHANNELS;
    const __half* Bg = g_f2h + ((size_t)b * NPAD + nt * 128) * CHANNELS;

    // per-thread cp.async assignment: 2 chunks of 16B for A, 2 for B per stage
    const int q0 = tid * 2, q1 = tid * 2 + 1;
    const int r0 = q0 >> 2, c0 = q0 & 3;
    const int r1 = q1 >> 2, c1 = q1 & 3;

    float acc[4][4][4];
    #pragma unroll
    for (int i = 0; i < 4; i++)
        #pragma unroll
        for (int j = 0; j < 4; j++)
            #pragma unroll
            for (int k = 0; k < 4; k++) acc[i][j][k] = 0.0f;

    auto issue = [&](int kt, int stage) {
        const uint32_t sA = sbase + stage * 2 * TILE_B;
        const uint32_t sB = sA + TILE_B;
        const int kh = kt * BK;                       // k offset in halves
        cp_async16(sA + r0 * SRB + c0 * 16, Ag + r0 * CHANNELS + kh + c0 * 8);
        cp_async16(sA + r1 * SRB + c1 * 16, Ag + r1 * CHANNELS + kh + c1 * 8);
        cp_async16(sB + r0 * SRB + c0 * 16, Bg + r0 * CHANNELS + kh + c0 * 8);
        cp_async16(sB + r1 * SRB + c1 * 16, Bg + r1 * CHANNELS + kh + c1 * 8);
        cp_commit();
    };

    issue(0, 0);
    issue(1, 1);

    // ldmatrix base offsets
    const int a_row = wm * 64 + (lane & 15);          // + mi*16
    const int a_kh  = (lane >> 4) * 8;                // + s*16 (halves)
    const int b_row = wn * 32 + (lane & 7);           // + ni*8
    const int b_kh  = ((lane >> 3) & 1) * 8;          // + s*16

    #pragma unroll
    for (int kt = 0; kt < 8; kt++) {
        if (kt < 7) cp_wait<1>(); else cp_wait<0>();
        __syncthreads();          // stage kt ready for all; stage (kt+2)%3 free
        if (kt + 2 < 8) issue(kt + 2, (kt + 2) % 3);

        const int stage = kt % 3;
        const uint32_t sA = sbase + stage * 2 * TILE_B;
        const uint32_t sB = sA + TILE_B;

        #pragma unroll
        for (int s = 0; s < 2; s++) {                 // two k16 steps per BK
            uint32_t afr[4][4], bfr[4][2];
            #pragma unroll
            for (int mi = 0; mi < 4; mi++)
                ldsm_x4(afr[mi], sA + (a_row + mi * 16) * SRB + (a_kh + s * 16) * 2);
            #pragma unroll
            for (int ni = 0; ni < 4; ni++)
                ldsm_x2(bfr[ni], sB + (b_row + ni * 8) * SRB + (b_kh + s * 16) * 2);
            #pragma unroll
            for (int mi = 0; mi < 4; mi++)
                #pragma unroll
                for (int ni = 0; ni < 4; ni++)
                    mma16816(acc[mi][ni], afr[mi], bfr[ni]);
        }
    }

    // epilogue: fp16 packed stores (half2 = 4B, contiguous 64B per row segment)
    const int gid = lane >> 2, tig = lane & 3;
    #pragma unroll
    for (int mi = 0; mi < 4; mi++) {
        const size_t row = (size_t)b * HW + mt * 128 + wm * 64 + mi * 16 + gid;
        __half* Cr = g_C + row * NPAD + nt * 128 + wn * 32 + tig * 2;
        #pragma unroll
        for (int ni = 0; ni < 4; ni++) {
            *(__half2*)(Cr + ni * 8)            = __floats2half2_rn(acc[mi][ni][0], acc[mi][ni][1]);
            *(__half2*)(Cr + 8 * NPAD + ni * 8) = __floats2half2_rn(acc[mi][ni][2], acc[mi][ni][3]);
        }
    }
}

// ============================ sampler =======================================
// One warp per pixel, 8 pixels/CTA: gather 10x10 corner grids from g_C rows,
// bilinear-interp 81 samples/level, coalesced channel-major store.
__global__ void __launch_bounds__(256) corr_sample(const float* __restrict__ cc,
                                                   float* __restrict__ out) {
    const int tid = threadIdx.x, warp = tid >> 5, lane = tid & 31;
    const int p = blockIdx.x * 8 + warp;
    const int b = p >> 12, pix = p & 4095;

    __shared__ float G[8][4][100];
    __shared__ float OB[8][324];

    const float cx = cc[(b * 2 + 0) * HW + pix];
    const float cy = cc[(b * 2 + 1) * HW + pix];
    const __half* Crow = g_C + ((size_t)b * HW + pix) * NPAD;
    const int off[4] = {0, 4096, 5120, 5376};

    #pragma unroll
    for (int lvl = 0; lvl < 4; lvl++) {
        const int size = 64 >> lvl;
        const float inv = 1.0f / (float)(1 << lvl);
        const float cxl = cx * inv, cyl = cy * inv;
        const int ix0 = (int)floorf(cxl) - 4;
        const int iy0 = (int)floorf(cyl) - 4;
        const __half* base = Crow + off[lvl];
        #pragma unroll
        for (int c = lane; c < 100; c += 32) {
            const int j = c / 10, i = c - j * 10;
            const int ix = ix0 + i, iy = iy0 + j;
            const bool valid = ((unsigned)ix < (unsigned)size) && ((unsigned)iy < (unsigned)size);
            G[warp][lvl][c] = valid ? __half2float(base[iy * size + ix]) : 0.0f;
        }
    }
    __syncwarp();

    #pragma unroll
    for (int lvl = 0; lvl < 4; lvl++) {
        const float inv = 1.0f / (float)(1 << lvl);
        const float cxl = cx * inv, cyl = cy * inv;
        const float fx = cxl - floorf(cxl);
        const float fy = cyl - floorf(cyl);
        for (int s = lane; s < 81; s += 32) {
            const int si = s / 9, sj = s - si * 9;   // si -> x offset, sj -> y offset
            const float g00 = G[warp][lvl][sj * 10 + si];
            const float g01 = G[warp][lvl][sj * 10 + si + 1];
            const float g10 = G[warp][lvl][(sj + 1) * 10 + si];
            const float g11 = G[warp][lvl][(sj + 1) * 10 + si + 1];
            OB[warp][lvl * 81 + s] = (1.0f - fy) * ((1.0f - fx) * g00 + fx * g01)
                                   + fy * ((1.0f - fx) * g10 + fx * g11);
        }
    }
    __syncthreads();

    const int pix0 = (blockIdx.x * 8) & 4095;
    const int bb = (blockIdx.x * 8) >> 12;
    for (int idx = tid; idx < 324 * 8; idx += 256) {
        const int ch = idx >> 3, pp = idx & 7;
        out[((size_t)bb * 324 + ch) * HW + pix0 + pp] = OB[pp][ch];
    }
}

// ===========================================================================
extern "C" void kernel_launch(void* const* d_in, const int* in_sizes, int n_in,
                              void* d_out, int out_size) {
    const float* fmap1 = (const float*)d_in[0];
    const float* fmap2 = (const float*)d_in[1];
    const float* cc    = (const float*)d_in[2];
    float* out = (float*)d_out;

    static int configured = 0;
    if (!configured) {
        cudaFuncSetAttribute(gemm_tile, cudaFuncAttributeMaxDynamicSharedMemorySize, GEMM_SMEM);
        configured = 1;
    }

    dim3 tgrid(HW / 32, CHANNELS / 32, BATCH);
    dim3 tblk(32, 8);
    cvt_transpose<<<tgrid, tblk>>>(fmap1, 0);
    cvt_transpose<<<tgrid, tblk>>>(fmap2, 1);

    pool_level<<<BATCH * 32 * 32, CHANNELS>>>(0,    4096, 32);
    pool_level<<<BATCH * 16 * 16, CHANNELS>>>(4096, 5120, 16);
    pool_level<<<BATCH * 8 * 8,   CHANNELS>>>(5120, 5376, 8);
    zero_pad<<<128, 256>>>();

    gemm_tile<<<dim3(43, 32, BATCH), 256, GEMM_SMEM>>>();

    corr_sample<<<(BATCH * HW) / 8, 256>>>(cc, out);
}

// round 5
// speedup vs baseline: 10.2735x; 1.6200x over previous
#include <cuda_runtime.h>
#include <cuda_fp16.h>
#include <cstdint>

#define CHANNELS 256
#define HW 4096
#define BATCH 2
#define F2COLS 5504            // padded pyramid cols per batch (uses 5440)
// level offsets: L0 0 (64x64), L1 4096 (32x32), L2 5120 (16x16), L3 5376 (8x8)
#define WSTRIDE 688            // per-pixel window stride (halves): 290+170+122+106 padded

__device__ __align__(16) __half g_f1h[BATCH * HW * CHANNELS];      // [b][m][k], scaled 1/16
__device__ __align__(16) __half g_f2h[BATCH * F2COLS * CHANNELS];  // [b][col][k]
__device__ __align__(16) __half g_W[(size_t)BATCH * HW * WSTRIDE]; // per-pixel windows (~11 MB)
__device__ int g_binstart[128];
__device__ int g_bincnt[128];
__device__ int g_blist[BATCH * HW];   // sorted pixel ids
__device__ int g_pos[BATCH * HW];     // pixel -> sorted position

// ===================== helpers ========================
__device__ __forceinline__ uint32_t smem_u32(const void* p) {
    uint32_t a;
    asm("{ .reg .u64 t; cvta.to.shared.u64 t, %1; cvt.u32.u64 %0, t; }" : "=r"(a) : "l"(p));
    return a;
}
__device__ __forceinline__ void cp_async16(uint32_t s, const void* g) {
    asm volatile("cp.async.cg.shared.global [%0], [%1], 16;" :: "r"(s), "l"(g));
}
__device__ __forceinline__ void cp_commit() { asm volatile("cp.async.commit_group;"); }
template <int N> __device__ __forceinline__ void cp_wait() {
    asm volatile("cp.async.wait_group %0;" :: "n"(N));
}
__device__ __forceinline__ void ldsm_x4(uint32_t* r, uint32_t addr) {
    asm volatile("ldmatrix.sync.aligned.m8n8.x4.shared.b16 {%0,%1,%2,%3}, [%4];"
                 : "=r"(r[0]), "=r"(r[1]), "=r"(r[2]), "=r"(r[3]) : "r"(addr));
}
__device__ __forceinline__ void ldsm_x2(uint32_t* r, uint32_t addr) {
    asm volatile("ldmatrix.sync.aligned.m8n8.x2.shared.b16 {%0,%1}, [%2];"
                 : "=r"(r[0]), "=r"(r[1]) : "r"(addr));
}
__device__ __forceinline__ void mma16816(float* c, const uint32_t* a, const uint32_t* b) {
    asm volatile("mma.sync.aligned.m16n8k16.row.col.f32.f16.f16.f32 "
                 "{%0,%1,%2,%3}, {%4,%5,%6,%7}, {%8,%9}, {%0,%1,%2,%3};"
                 : "+f"(c[0]), "+f"(c[1]), "+f"(c[2]), "+f"(c[3])
                 : "r"(a[0]), "r"(a[1]), "r"(a[2]), "r"(a[3]), "r"(b[0]), "r"(b[1]));
}

// ======================= prep: transpose + fp16 convert =====================
__global__ void cvt_transpose(const float* __restrict__ src, int which) {
    __shared__ float tile[32][33];
    __half* dst = which ? g_f2h : g_f1h;
    const float scale = which ? 1.0f : 0.0625f;      // 1/sqrt(256) folded into f1
    const int bstride = which ? (F2COLS * CHANNELS) : (HW * CHANNELS);

    const int b = blockIdx.z, p0 = blockIdx.x * 32, c0 = blockIdx.y * 32;
    const float* s = src + (size_t)b * CHANNELS * HW;
    #pragma unroll
    for (int r = threadIdx.y; r < 32; r += 8)
        tile[r][threadIdx.x] = s[(c0 + r) * HW + p0 + threadIdx.x] * scale;
    __syncthreads();
    __half* d = dst + (size_t)b * bstride;
    #pragma unroll
    for (int r = threadIdx.y; r < 32; r += 8)
        d[(p0 + r) * CHANNELS + c0 + threadIdx.x] = __float2half(tile[threadIdx.x][r]);
}

__global__ void pool_level(int src_off, int dst_off, int S) {
    const int col = blockIdx.x;
    const int b = col / (S * S);
    const int r = col - b * S * S;
    const int Y = r / S, X = r - Y * S;
    const int c = threadIdx.x;
    const __half* s = g_f2h + ((size_t)b * F2COLS + src_off + (2 * Y) * (2 * S) + 2 * X) * CHANNELS;
    float v = __half2float(s[c]) + __half2float(s[CHANNELS + c]) +
              __half2float(s[(2 * S) * CHANNELS + c]) +
              __half2float(s[(2 * S) * CHANNELS + CHANNELS + c]);
    g_f2h[((size_t)b * F2COLS + dst_off + r) * CHANNELS + c] = __float2half(0.25f * v);
}

// ============================ binning =======================================
// Single block: histogram over 128 bins (batch x 8x8 cell), scan, scatter.
__global__ void __launch_bounds__(1024) bin_pixels(const float* __restrict__ cc) {
    __shared__ int scnt[128], sstart[128];
    const int tid = threadIdx.x;
    if (tid < 128) scnt[tid] = 0;
    __syncthreads();
    int mycell[8];
    #pragma unroll
    for (int i = 0; i < 8; i++) {
        const int p = tid + i * 1024;
        const int b = p >> 12, pix = p & 4095;
        const float cx = cc[(b * 2 + 0) * HW + pix];
        const float cy = cc[(b * 2 + 1) * HW + pix];
        const int CX = min(7, max(0, ((int)floorf(cx)) >> 3));
        const int CY = min(7, max(0, ((int)floorf(cy)) >> 3));
        mycell[i] = b * 64 + CY * 8 + CX;
        atomicAdd(&scnt[mycell[i]], 1);
    }
    __syncthreads();
    if (tid == 0) {
        int acc = 0;
        for (int k = 0; k < 128; k++) {
            sstart[k] = acc;
            g_binstart[k] = acc;
            g_bincnt[k] = scnt[k];
            acc += scnt[k];
        }
    }
    __syncthreads();
    if (tid < 128) scnt[tid] = 0;   // reuse as cursor
    __syncthreads();
    #pragma unroll
    for (int i = 0; i < 8; i++) {
        const int p = tid + i * 1024;
        const int pos = sstart[mycell[i]] + atomicAdd(&scnt[mycell[i]], 1);
        g_blist[pos] = p;
        g_pos[p] = pos;
    }
}

// ============================ binned window GEMM ============================
// For one (bin, level, 64-row chunk): W[row][n] = sum_k f1[pix_row][k] * f2[col(n)][k]
// 8 warps as 2(m) x 4(n); warp tile 32 x NW. 3-stage cp.async pipeline.
#define BK 32
#define SRB 80                  // smem row stride bytes (32 halves + pad)

template <int WW, int NPAD, int WBASE, int LVLOFF, int SIZE, int CELLW>
__global__ void __launch_bounds__(256) binned_gemm() {
    constexpr int NL = WW * WW;
    constexpr int NW = NPAD / 4;
    constexpr int NI = NW / 8;
    constexpr int ATILE = 64 * SRB;
    constexpr int BTILE = NPAD * SRB;
    constexpr int STAGE = ATILE + BTILE;

    extern __shared__ __align__(16) char smem[];
    __shared__ int s_colidx[NPAD];
    __shared__ int s_plist[64];

    const int bin = blockIdx.x, chunk = blockIdx.y;
    const int start = g_binstart[bin];
    const int cnt = g_bincnt[bin];
    int rows = cnt - chunk * 64;
    if (rows <= 0) return;
    if (rows > 64) rows = 64;

    const int tid = threadIdx.x, wid = tid >> 5, lane = tid & 31;
    const int wm = wid & 1, wn = wid >> 1;
    const int b = bin >> 6, cell = bin & 63;
    const int CY = cell >> 3, CX = cell & 7;
    const int wx0 = CELLW * CX - 4, wy0 = CELLW * CY - 4;

    // window column -> pyramid column offset (halves), clamped (invalid masked later)
    for (int n = tid; n < NPAD; n += 256) {
        int wy = n / WW, wx = n - wy * WW;
        int iy = min(SIZE - 1, max(0, wy0 + wy));
        int ix = min(SIZE - 1, max(0, wx0 + wx));
        s_colidx[n] = (LVLOFF + iy * SIZE + ix) * CHANNELS;
    }
    if (tid < 64) {
        int g = start + chunk * 64 + tid;
        s_plist[tid] = g_blist[tid < rows ? g : start];
    }
    __syncthreads();

    const uint32_t sbase = smem_u32(smem);
    const __half* f2b = g_f2h + (size_t)b * F2COLS * CHANNELS;

    auto issue = [&](int kt, int stage) {
        const uint32_t sA = sbase + stage * STAGE;
        const uint32_t sB = sA + ATILE;
        const int kh = kt * BK;
        {   // A: 64 rows x 4 chunks = 256
            const int r = tid >> 2, c = tid & 3;
            cp_async16(sA + r * SRB + c * 16,
                       g_f1h + (size_t)s_plist[r] * CHANNELS + kh + c * 8);
        }
        #pragma unroll
        for (int i = 0; i < NPAD / 64; i++) {   // B: NPAD cols x 4 chunks
            const int q = tid + i * 256;
            const int n = q >> 2, c = q & 3;
            cp_async16(sB + n * SRB + c * 16, f2b + s_colidx[n] + kh + c * 8);
        }
        cp_commit();
    };

    float acc[2][NI][4];
    #pragma unroll
    for (int i = 0; i < 2; i++)
        #pragma unroll
        for (int j = 0; j < NI; j++)
            #pragma unroll
            for (int e = 0; e < 4; e++) acc[i][j][e] = 0.0f;

    issue(0, 0);
    issue(1, 1);

    const int a_row = wm * 32 + (lane & 15);
    const int a_kh = (lane >> 4) * 8;
    const int b_row = wn * NW + (lane & 7);
    const int b_kh = ((lane >> 3) & 1) * 8;

    #pragma unroll
    for (int kt = 0; kt < 8; kt++) {
        if (kt < 7) cp_wait<1>(); else cp_wait<0>();
        __syncthreads();
        if (kt + 2 < 8) issue(kt + 2, (kt + 2) % 3);

        const int stage = kt % 3;
        const uint32_t sA = sbase + stage * STAGE;
        const uint32_t sB = sA + ATILE;

        #pragma unroll
        for (int s = 0; s < 2; s++) {
            uint32_t afr[2][4], bfr[NI][2];
            #pragma unroll
            for (int mi = 0; mi < 2; mi++)
                ldsm_x4(afr[mi], sA + (a_row + mi * 16) * SRB + (a_kh + s * 16) * 2);
            #pragma unroll
            for (int ni = 0; ni < NI; ni++)
                ldsm_x2(bfr[ni], sB + (b_row + ni * 8) * SRB + (b_kh + s * 16) * 2);
            #pragma unroll
            for (int mi = 0; mi < 2; mi++)
                #pragma unroll
                for (int ni = 0; ni < NI; ni++)
                    mma16816(acc[mi][ni], afr[mi], bfr[ni]);
        }
    }

    // epilogue: fp16 windows, guarded by rows/NL
    const int gid = lane >> 2, tig = lane & 3;
    #pragma unroll
    for (int mi = 0; mi < 2; mi++) {
        const int r0 = wm * 32 + mi * 16 + gid;
        const int r1 = r0 + 8;
        __half* W0 = g_W + (size_t)(start + chunk * 64 + r0) * WSTRIDE + WBASE;
        __half* W1 = g_W + (size_t)(start + chunk * 64 + r1) * WSTRIDE + WBASE;
        #pragma unroll
        for (int ni = 0; ni < NI; ni++) {
            const int cb = wn * NW + ni * 8 + tig * 2;
            if (cb + 1 < NL) {
                if (r0 < rows) *(__half2*)(W0 + cb) = __floats2half2_rn(acc[mi][ni][0], acc[mi][ni][1]);
                if (r1 < rows) *(__half2*)(W1 + cb) = __floats2half2_rn(acc[mi][ni][2], acc[mi][ni][3]);
            } else if (cb < NL) {
                if (r0 < rows) W0[cb] = __float2half(acc[mi][ni][0]);
                if (r1 < rows) W1[cb] = __float2half(acc[mi][ni][2]);
            }
        }
    }
}

// ============================ sampler =======================================
// One warp per pixel, 8 pixels/CTA; corners read from the pixel's compact window.
__global__ void __launch_bounds__(256) corr_sample(const float* __restrict__ cc,
                                                   float* __restrict__ out) {
    const int tid = threadIdx.x, warp = tid >> 5, lane = tid & 31;
    const int p = blockIdx.x * 8 + warp;
    const int b = p >> 12, pix = p & 4095;

    __shared__ float G[8][4][100];
    __shared__ float OB[8][324];

    const float cx = cc[(b * 2 + 0) * HW + pix];
    const float cy = cc[(b * 2 + 1) * HW + pix];
    const int CX = min(7, max(0, ((int)floorf(cx)) >> 3));
    const int CY = min(7, max(0, ((int)floorf(cy)) >> 3));
    const __half* Wp = g_W + (size_t)g_pos[p] * WSTRIDE;

    const int WWl[4]   = {17, 13, 11, 10};
    const int basel[4] = {0, 290, 460, 582};
    const int sizel[4] = {64, 32, 16, 8};
    const int cwl[4]   = {8, 4, 2, 1};

    #pragma unroll
    for (int lvl = 0; lvl < 4; lvl++) {
        const float inv = 1.0f / (float)(1 << lvl);
        const float cxl = cx * inv, cyl = cy * inv;
        const int fxi = (int)floorf(cxl), fyi = (int)floorf(cyl);
        const int dx = fxi - cwl[lvl] * CX;     // in [0, cellW-1]
        const int dy = fyi - cwl[lvl] * CY;
        const int WWc = WWl[lvl], sz = sizel[lvl];
        const __half* base = Wp + basel[lvl];
        #pragma unroll
        for (int c = lane; c < 100; c += 32) {
            const int j = c / 10, i = c - j * 10;
            const int ix = fxi - 4 + i, iy = fyi - 4 + j;
            const bool valid = ((unsigned)ix < (unsigned)sz) && ((unsigned)iy < (unsigned)sz);
            G[warp][lvl][c] = valid ? __half2float(base[(dy + j) * WWc + dx + i]) : 0.0f;
        }
    }
    __syncwarp();

    #pragma unroll
    for (int lvl = 0; lvl < 4; lvl++) {
        const float inv = 1.0f / (float)(1 << lvl);
        const float cxl = cx * inv, cyl = cy * inv;
        const float fx = cxl - floorf(cxl);
        const float fy = cyl - floorf(cyl);
        for (int s = lane; s < 81; s += 32) {
            const int si = s / 9, sj = s - si * 9;  // si -> x offset, sj -> y offset
            const float g00 = G[warp][lvl][sj * 10 + si];
            const float g01 = G[warp][lvl][sj * 10 + si + 1];
            const float g10 = G[warp][lvl][(sj + 1) * 10 + si];
            const float g11 = G[warp][lvl][(sj + 1) * 10 + si + 1];
            OB[warp][lvl * 81 + s] = (1.0f - fy) * ((1.0f - fx) * g00 + fx * g01)
                                   + fy * ((1.0f - fx) * g10 + fx * g11);
        }
    }
    __syncthreads();

    const int pix0 = (blockIdx.x * 8) & 4095;
    const int bb = (blockIdx.x * 8) >> 12;
    for (int idx = tid; idx < 324 * 8; idx += 256) {
        const int ch = idx >> 3, pp = idx & 7;
        out[((size_t)bb * 324 + ch) * HW + pix0 + pp] = OB[pp][ch];
    }
}

// ===========================================================================
#define SMEM_L0 (3 * (64 * SRB + 320 * SRB))   // 92160
#define SMEM_L1 (3 * (64 * SRB + 192 * SRB))   // 61440
#define SMEM_L2 (3 * (64 * SRB + 128 * SRB))   // 46080

extern "C" void kernel_launch(void* const* d_in, const int* in_sizes, int n_in,
                              void* d_out, int out_size) {
    const float* fmap1 = (const float*)d_in[0];
    const float* fmap2 = (const float*)d_in[1];
    const float* cc    = (const float*)d_in[2];
    float* out = (float*)d_out;

    static int configured = 0;
    if (!configured) {
        cudaFuncSetAttribute(binned_gemm<17, 320, 0, 0, 64, 8>,
                             cudaFuncAttributeMaxDynamicSharedMemorySize, SMEM_L0);
        cudaFuncSetAttribute(binned_gemm<13, 192, 290, 4096, 32, 4>,
                             cudaFuncAttributeMaxDynamicSharedMemorySize, SMEM_L1);
        cudaFuncSetAttribute(binned_gemm<11, 128, 460, 5120, 16, 2>,
                             cudaFuncAttributeMaxDynamicSharedMemorySize, SMEM_L2);
        cudaFuncSetAttribute(binned_gemm<10, 128, 582, 5376, 8, 1>,
                             cudaFuncAttributeMaxDynamicSharedMemorySize, SMEM_L2);
        configured = 1;
    }

    bin_pixels<<<1, 1024>>>(cc);

    dim3 tgrid(HW / 32, CHANNELS / 32, BATCH);
    dim3 tblk(32, 8);
    cvt_transpose<<<tgrid, tblk>>>(fmap1, 0);
    cvt_transpose<<<tgrid, tblk>>>(fmap2, 1);

    pool_level<<<BATCH * 32 * 32, CHANNELS>>>(0,    4096, 32);
    pool_level<<<BATCH * 16 * 16, CHANNELS>>>(4096, 5120, 16);
    pool_level<<<BATCH * 8 * 8,   CHANNELS>>>(5120, 5376, 8);

    dim3 ggrid(128, 4);
    binned_gemm<17, 320, 0, 0, 64, 8><<<ggrid, 256, SMEM_L0>>>();
    binned_gemm<13, 192, 290, 4096, 32, 4><<<ggrid, 256, SMEM_L1>>>();
    binned_gemm<11, 128, 460, 5120, 16, 2><<<ggrid, 256, SMEM_L2>>>();
    binned_gemm<10, 128, 582, 5376, 8, 1><<<ggrid, 256, SMEM_L2>>>();

    corr_sample<<<(BATCH * HW) / 8, 256>>>(cc, out);
}

// round 6
// speedup vs baseline: 16.2703x; 1.5837x over previous
#include <cuda_runtime.h>
#include <cuda_fp16.h>
#include <cstdint>

#define CHANNELS 256
#define HW 4096
#define BATCH 2
#define F2COLS 5504            // padded pyramid cols per batch (uses 5440)
// level offsets: L0 0 (64x64), L1 4096 (32x32), L2 5120 (16x16), L3 5376 (8x8)
#define WSTRIDE 688            // per-pixel window stride (halves): 290+170+122+106 padded

__device__ __align__(16) __half g_f1h[BATCH * HW * CHANNELS];      // [b][m][k], scaled 1/16
__device__ __align__(16) __half g_f2h[BATCH * F2COLS * CHANNELS];  // [b][col][k]
__device__ __align__(16) __half g_W[(size_t)BATCH * HW * WSTRIDE]; // per-pixel windows (~11 MB)
__device__ int g_binstart[128];
__device__ int g_bincnt[128];
__device__ int g_blist[BATCH * HW];   // sorted pixel ids
__device__ int g_pos[BATCH * HW];     // pixel -> sorted position

// ===================== helpers ========================
__device__ __forceinline__ uint32_t smem_u32(const void* p) {
    uint32_t a;
    asm("{ .reg .u64 t; cvta.to.shared.u64 t, %1; cvt.u32.u64 %0, t; }" : "=r"(a) : "l"(p));
    return a;
}
__device__ __forceinline__ void cp_async16(uint32_t s, const void* g) {
    asm volatile("cp.async.cg.shared.global [%0], [%1], 16;" :: "r"(s), "l"(g));
}
__device__ __forceinline__ void cp_commit() { asm volatile("cp.async.commit_group;"); }
template <int N> __device__ __forceinline__ void cp_wait() {
    asm volatile("cp.async.wait_group %0;" :: "n"(N));
}
__device__ __forceinline__ void ldsm_x4(uint32_t* r, uint32_t addr) {
    asm volatile("ldmatrix.sync.aligned.m8n8.x4.shared.b16 {%0,%1,%2,%3}, [%4];"
                 : "=r"(r[0]), "=r"(r[1]), "=r"(r[2]), "=r"(r[3]) : "r"(addr));
}
__device__ __forceinline__ void ldsm_x2(uint32_t* r, uint32_t addr) {
    asm volatile("ldmatrix.sync.aligned.m8n8.x2.shared.b16 {%0,%1}, [%2];"
                 : "=r"(r[0]), "=r"(r[1]) : "r"(addr));
}
__device__ __forceinline__ void mma16816(float* c, const uint32_t* a, const uint32_t* b) {
    asm volatile("mma.sync.aligned.m16n8k16.row.col.f32.f16.f16.f32 "
                 "{%0,%1,%2,%3}, {%4,%5,%6,%7}, {%8,%9}, {%0,%1,%2,%3};"
                 : "+f"(c[0]), "+f"(c[1]), "+f"(c[2]), "+f"(c[3])
                 : "r"(a[0]), "r"(a[1]), "r"(a[2]), "r"(a[3]), "r"(b[0]), "r"(b[1]));
}

// ======================= prep: transpose + fp16 convert =====================
__global__ void cvt_transpose(const float* __restrict__ src, int which) {
    __shared__ float tile[32][33];
    __half* dst = which ? g_f2h : g_f1h;
    const float scale = which ? 1.0f : 0.0625f;      // 1/sqrt(256) folded into f1
    const int bstride = which ? (F2COLS * CHANNELS) : (HW * CHANNELS);

    const int b = blockIdx.z, p0 = blockIdx.x * 32, c0 = blockIdx.y * 32;
    const float* s = src + (size_t)b * CHANNELS * HW;
    #pragma unroll
    for (int r = threadIdx.y; r < 32; r += 8)
        tile[r][threadIdx.x] = s[(c0 + r) * HW + p0 + threadIdx.x] * scale;
    __syncthreads();
    __half* d = dst + (size_t)b * bstride;
    #pragma unroll
    for (int r = threadIdx.y; r < 32; r += 8)
        d[(p0 + r) * CHANNELS + c0 + threadIdx.x] = __float2half(tile[threadIdx.x][r]);
}

__global__ void pool_level(int src_off, int dst_off, int S) {
    const int col = blockIdx.x;
    const int b = col / (S * S);
    const int r = col - b * S * S;
    const int Y = r / S, X = r - Y * S;
    const int c = threadIdx.x;
    const __half* s = g_f2h + ((size_t)b * F2COLS + src_off + (2 * Y) * (2 * S) + 2 * X) * CHANNELS;
    float v = __half2float(s[c]) + __half2float(s[CHANNELS + c]) +
              __half2float(s[(2 * S) * CHANNELS + c]) +
              __half2float(s[(2 * S) * CHANNELS + CHANNELS + c]);
    g_f2h[((size_t)b * F2COLS + dst_off + r) * CHANNELS + c] = __float2half(0.25f * v);
}

// ============================ binning =======================================
__global__ void __launch_bounds__(1024) bin_pixels(const float* __restrict__ cc) {
    __shared__ int scnt[128], sstart[128];
    const int tid = threadIdx.x;
    if (tid < 128) scnt[tid] = 0;
    __syncthreads();
    int mycell[8];
    #pragma unroll
    for (int i = 0; i < 8; i++) {
        const int p = tid + i * 1024;
        const int b = p >> 12, pix = p & 4095;
        const float cx = cc[(b * 2 + 0) * HW + pix];
        const float cy = cc[(b * 2 + 1) * HW + pix];
        const int CX = min(7, max(0, ((int)floorf(cx)) >> 3));
        const int CY = min(7, max(0, ((int)floorf(cy)) >> 3));
        mycell[i] = b * 64 + CY * 8 + CX;
        atomicAdd(&scnt[mycell[i]], 1);
    }
    __syncthreads();
    if (tid == 0) {
        int acc = 0;
        for (int k = 0; k < 128; k++) {
            sstart[k] = acc;
            g_binstart[k] = acc;
            g_bincnt[k] = scnt[k];
            acc += scnt[k];
        }
    }
    __syncthreads();
    if (tid < 128) scnt[tid] = 0;   // reuse as cursor
    __syncthreads();
    #pragma unroll
    for (int i = 0; i < 8; i++) {
        const int p = tid + i * 1024;
        const int pos = sstart[mycell[i]] + atomicAdd(&scnt[mycell[i]], 1);
        g_blist[pos] = p;
        g_pos[p] = pos;
    }
}

// ============================ binned window GEMM ============================
// One (bin, 64-row chunk, n-split). 8 warps 2(m) x 4(n); warp tile 32 x NW.
#define BK 32
#define SRB 80

template <int WW, int NPC, int WBASE, int LVLOFF, int SIZE, int CELLW>
__global__ void __launch_bounds__(256) binned_gemm() {
    constexpr int NL = WW * WW;
    constexpr int NW = NPC / 4;
    constexpr int NI = NW / 8;
    constexpr int ATILE = 64 * SRB;
    constexpr int BTILE = NPC * SRB;
    constexpr int STAGE = ATILE + BTILE;

    extern __shared__ __align__(16) char smem[];
    __shared__ int s_colidx[NPC];
    __shared__ int s_plist[64];

    const int bin = blockIdx.x, chunk = blockIdx.y;
    const int nbase = blockIdx.z * NPC;
    const int start = g_binstart[bin];
    const int cnt = g_bincnt[bin];
    int rows = cnt - chunk * 64;
    if (rows <= 0) return;
    if (rows > 64) rows = 64;

    const int tid = threadIdx.x, wid = tid >> 5, lane = tid & 31;
    const int wm = wid & 1, wn = wid >> 1;
    const int b = bin >> 6, cell = bin & 63;
    const int CY = cell >> 3, CX = cell & 7;
    const int wx0 = CELLW * CX - 4, wy0 = CELLW * CY - 4;

    for (int n = tid; n < NPC; n += 256) {
        const int ng = nbase + n;
        const int wy = ng / WW, wx = ng - wy * WW;
        const int iy = min(SIZE - 1, max(0, wy0 + wy));
        const int ix = min(SIZE - 1, max(0, wx0 + wx));
        s_colidx[n] = (LVLOFF + iy * SIZE + ix) * CHANNELS;
    }
    if (tid < 64) {
        const int g = start + chunk * 64 + tid;
        s_plist[tid] = g_blist[tid < rows ? g : start];
    }
    __syncthreads();

    const uint32_t sbase = smem_u32(smem);
    const __half* f2b = g_f2h + (size_t)b * F2COLS * CHANNELS;

    auto issue = [&](int kt, int stage) {
        const uint32_t sA = sbase + stage * STAGE;
        const uint32_t sB = sA + ATILE;
        const int kh = kt * BK;
        {   // A: 64 rows x 4 chunks = 256
            const int r = tid >> 2, c = tid & 3;
            cp_async16(sA + r * SRB + c * 16,
                       g_f1h + (size_t)s_plist[r] * CHANNELS + kh + c * 8);
        }
        for (int q = tid; q < NPC * 4; q += 256) {
            const int n = q >> 2, c = q & 3;
            cp_async16(sB + n * SRB + c * 16, f2b + s_colidx[n] + kh + c * 8);
        }
        cp_commit();
    };

    float acc[2][NI][4];
    #pragma unroll
    for (int i = 0; i < 2; i++)
        #pragma unroll
        for (int j = 0; j < NI; j++)
            #pragma unroll
            for (int e = 0; e < 4; e++) acc[i][j][e] = 0.0f;

    issue(0, 0);
    issue(1, 1);

    const int a_row = wm * 32 + (lane & 15);
    const int a_kh = (lane >> 4) * 8;
    const int b_row = wn * NW + (lane & 7);
    const int b_kh = ((lane >> 3) & 1) * 8;

    #pragma unroll
    for (int kt = 0; kt < 8; kt++) {
        if (kt < 7) cp_wait<1>(); else cp_wait<0>();
        __syncthreads();
        if (kt + 2 < 8) issue(kt + 2, (kt + 2) % 3);

        const int stage = kt % 3;
        const uint32_t sA = sbase + stage * STAGE;
        const uint32_t sB = sA + ATILE;

        #pragma unroll
        for (int s = 0; s < 2; s++) {
            uint32_t afr[2][4], bfr[NI][2];
            #pragma unroll
            for (int mi = 0; mi < 2; mi++)
                ldsm_x4(afr[mi], sA + (a_row + mi * 16) * SRB + (a_kh + s * 16) * 2);
            #pragma unroll
            for (int ni = 0; ni < NI; ni++)
                ldsm_x2(bfr[ni], sB + (b_row + ni * 8) * SRB + (b_kh + s * 16) * 2);
            #pragma unroll
            for (int mi = 0; mi < 2; mi++)
                #pragma unroll
                for (int ni = 0; ni < NI; ni++)
                    mma16816(acc[mi][ni], afr[mi], bfr[ni]);
        }
    }

    const int gid = lane >> 2, tig = lane & 3;
    #pragma unroll
    for (int mi = 0; mi < 2; mi++) {
        const int r0 = wm * 32 + mi * 16 + gid;
        const int r1 = r0 + 8;
        __half* W0 = g_W + (size_t)(start + chunk * 64 + r0) * WSTRIDE + WBASE;
        __half* W1 = g_W + (size_t)(start + chunk * 64 + r1) * WSTRIDE + WBASE;
        #pragma unroll
        for (int ni = 0; ni < NI; ni++) {
            const int cbg = nbase + wn * NW + ni * 8 + tig * 2;
            if (cbg + 1 < NL) {
                if (r0 < rows) *(__half2*)(W0 + cbg) = __floats2half2_rn(acc[mi][ni][0], acc[mi][ni][1]);
                if (r1 < rows) *(__half2*)(W1 + cbg) = __floats2half2_rn(acc[mi][ni][2], acc[mi][ni][3]);
            } else if (cbg < NL) {
                if (r0 < rows) W0[cbg] = __float2half(acc[mi][ni][0]);
                if (r1 < rows) W1[cbg] = __float2half(acc[mi][ni][2]);
            }
        }
    }
}

// ======================== per-level sampler =================================
template <int LVL, int WW, int WBASE, int SIZE, int CELLW>
__global__ void __launch_bounds__(256) sample_level(const float* __restrict__ cc,
                                                    float* __restrict__ out) {
    const int tid = threadIdx.x, warp = tid >> 5, lane = tid & 31;
    const int p = blockIdx.x * 8 + warp;
    const int b = p >> 12, pix = p & 4095;

    __shared__ float G[8][100];
    __shared__ float OB[8][81];

    const float cx = cc[(b * 2 + 0) * HW + pix];
    const float cy = cc[(b * 2 + 1) * HW + pix];
    const int CX = min(7, max(0, ((int)floorf(cx)) >> 3));
    const int CY = min(7, max(0, ((int)floorf(cy)) >> 3));
    const __half* base = g_W + (size_t)g_pos[p] * WSTRIDE + WBASE;

    const float inv = 1.0f / (float)(1 << LVL);
    const float cxl = cx * inv, cyl = cy * inv;
    const int fxi = (int)floorf(cxl), fyi = (int)floorf(cyl);
    const int dx = fxi - CELLW * CX;
    const int dy = fyi - CELLW * CY;

    #pragma unroll
    for (int c = lane; c < 100; c += 32) {
        const int j = c / 10, i = c - j * 10;
        const int ix = fxi - 4 + i, iy = fyi - 4 + j;
        const bool valid = ((unsigned)ix < (unsigned)SIZE) && ((unsigned)iy < (unsigned)SIZE);
        G[warp][c] = valid ? __half2float(base[(dy + j) * WW + dx + i]) : 0.0f;
    }
    __syncwarp();

    const float fx = cxl - floorf(cxl);
    const float fy = cyl - floorf(cyl);
    for (int s = lane; s < 81; s += 32) {
        const int si = s / 9, sj = s - si * 9;      // si -> x offset, sj -> y offset
        const float g00 = G[warp][sj * 10 + si];
        const float g01 = G[warp][sj * 10 + si + 1];
        const float g10 = G[warp][(sj + 1) * 10 + si];
        const float g11 = G[warp][(sj + 1) * 10 + si + 1];
        OB[warp][s] = (1.0f - fy) * ((1.0f - fx) * g00 + fx * g01)
                    + fy * ((1.0f - fx) * g10 + fx * g11);
    }
    __syncthreads();

    const int pix0 = (blockIdx.x * 8) & 4095;
    const int bb = (blockIdx.x * 8) >> 12;
    for (int idx = tid; idx < 81 * 8; idx += 256) {
        const int ch = idx >> 3, pp = idx & 7;
        out[((size_t)bb * 324 + LVL * 81 + ch) * HW + pix0 + pp] = OB[pp][ch];
    }
}

// ===========================================================================
#define SMEM_L0 (3 * ((64 + 160) * SRB))   // 53760
#define SMEM_L1 (3 * ((64 + 192) * SRB))   // 61440
#define SMEM_L2 (3 * ((64 + 128) * SRB))   // 46080

extern "C" void kernel_launch(void* const* d_in, const int* in_sizes, int n_in,
                              void* d_out, int out_size) {
    const float* fmap1 = (const float*)d_in[0];
    const float* fmap2 = (const float*)d_in[1];
    const float* cc    = (const float*)d_in[2];
    float* out = (float*)d_out;

    static cudaStream_t s1, s2, s3;
    static cudaEvent_t evRoot, evF1, evBin, evF2, evP1, evP2, evE1, evE2, evE3;
    static int inited = 0;
    if (!inited) {
        cudaStreamCreateWithFlags(&s1, cudaStreamNonBlocking);
        cudaStreamCreateWithFlags(&s2, cudaStreamNonBlocking);
        cudaStreamCreateWithFlags(&s3, cudaStreamNonBlocking);
        cudaEventCreateWithFlags(&evRoot, cudaEventDisableTiming);
        cudaEventCreateWithFlags(&evF1, cudaEventDisableTiming);
        cudaEventCreateWithFlags(&evBin, cudaEventDisableTiming);
        cudaEventCreateWithFlags(&evF2, cudaEventDisableTiming);
        cudaEventCreateWithFlags(&evP1, cudaEventDisableTiming);
        cudaEventCreateWithFlags(&evP2, cudaEventDisableTiming);
        cudaEventCreateWithFlags(&evE1, cudaEventDisableTiming);
        cudaEventCreateWithFlags(&evE2, cudaEventDisableTiming);
        cudaEventCreateWithFlags(&evE3, cudaEventDisableTiming);
        cudaFuncSetAttribute(binned_gemm<17, 160, 0, 0, 64, 8>,
                             cudaFuncAttributeMaxDynamicSharedMemorySize, SMEM_L0);
        cudaFuncSetAttribute(binned_gemm<13, 192, 290, 4096, 32, 4>,
                             cudaFuncAttributeMaxDynamicSharedMemorySize, SMEM_L1);
        cudaFuncSetAttribute(binned_gemm<11, 128, 460, 5120, 16, 2>,
                             cudaFuncAttributeMaxDynamicSharedMemorySize, SMEM_L2);
        cudaFuncSetAttribute(binned_gemm<10, 128, 582, 5376, 8, 1>,
                             cudaFuncAttributeMaxDynamicSharedMemorySize, SMEM_L2);
        inited = 1;
    }

    dim3 tgrid(HW / 32, CHANNELS / 32, BATCH);
    dim3 tblk(32, 8);

    cudaEventRecord(evRoot, 0);

    // s2: binning
    cudaStreamWaitEvent(s2, evRoot, 0);
    bin_pixels<<<1, 1024, 0, s2>>>(cc);
    cudaEventRecord(evBin, s2);

    // s1: f1 transpose
    cudaStreamWaitEvent(s1, evRoot, 0);
    cvt_transpose<<<tgrid, tblk, 0, s1>>>(fmap1, 0);
    cudaEventRecord(evF1, s1);

    // main: f2 transpose + pool chain
    cvt_transpose<<<tgrid, tblk>>>(fmap2, 1);
    cudaEventRecord(evF2, 0);
    pool_level<<<BATCH * 32 * 32, CHANNELS>>>(0, 4096, 32);
    cudaEventRecord(evP1, 0);
    pool_level<<<BATCH * 16 * 16, CHANNELS>>>(4096, 5120, 16);
    cudaEventRecord(evP2, 0);
    pool_level<<<BATCH * 8 * 8, CHANNELS>>>(5120, 5376, 8);

    // s3: level 0 (N split in 2) -> sampler 0
    cudaStreamWaitEvent(s3, evF2, 0);
    cudaStreamWaitEvent(s3, evF1, 0);
    cudaStreamWaitEvent(s3, evBin, 0);
    binned_gemm<17, 160, 0, 0, 64, 8><<<dim3(128, 4, 2), 256, SMEM_L0, s3>>>();
    sample_level<0, 17, 0, 64, 8><<<1024, 256, 0, s3>>>(cc, out);
    cudaEventRecord(evE3, s3);

    // s1: level 1 -> sampler 1 (f1 already on s1)
    cudaStreamWaitEvent(s1, evP1, 0);
    cudaStreamWaitEvent(s1, evBin, 0);
    binned_gemm<13, 192, 290, 4096, 32, 4><<<dim3(128, 4, 1), 256, SMEM_L1, s1>>>();
    sample_level<1, 13, 290, 32, 4><<<1024, 256, 0, s1>>>(cc, out);
    cudaEventRecord(evE1, s1);

    // s2: level 2 -> sampler 2 (bin already on s2)
    cudaStreamWaitEvent(s2, evP2, 0);
    cudaStreamWaitEvent(s2, evF1, 0);
    binned_gemm<11, 128, 460, 5120, 16, 2><<<dim3(128, 4, 1), 256, SMEM_L2, s2>>>();
    sample_level<2, 11, 460, 16, 2><<<1024, 256, 0, s2>>>(cc, out);
    cudaEventRecord(evE2, s2);

    // main: level 3 -> sampler 3 (after pool chain)
    cudaStreamWaitEvent(0, evF1, 0);
    cudaStreamWaitEvent(0, evBin, 0);
    binned_gemm<10, 128, 582, 5376, 8, 1><<<dim3(128, 4, 1), 256, SMEM_L2>>>();
    sample_level<3, 10, 582, 8, 1><<<1024, 256>>>(cc, out);

    // join all branches back into the origin stream
    cudaStreamWaitEvent(0, evE1, 0);
    cudaStreamWaitEvent(0, evE2, 0);
    cudaStreamWaitEvent(0, evE3, 0);
}